// round 5
// baseline (speedup 1.0000x reference)
#include <cuda_runtime.h>

// SSIM map: 3x3 mean filter (reflect pad 1) fused, fp32 in/out.
// Shapes fixed by the problem: N*C = planes, H=384, W=640.

#define HH 384
#define WW 640
#define STRIP 8          // output rows per thread
#define TPB 160          // threads per block: 160 * 4 cols = full width (640)

__device__ __forceinline__ int rrow(int r) {
    // reflect index for pad=1: -1 -> 1, H -> H-2
    return r < 0 ? -r : (r >= HH ? 2 * HH - 2 - r : r);
}

__device__ __forceinline__ void load_row6(const float* __restrict__ base,
                                          int c0, int cm1, int cp4,
                                          float dst[6]) {
    float4 v = *(const float4*)(base + c0);
    dst[0] = __ldg(base + cm1);
    dst[1] = v.x; dst[2] = v.y; dst[3] = v.z; dst[4] = v.w;
    dst[5] = __ldg(base + cp4);
}

__global__ __launch_bounds__(TPB)
void ssim_kernel(const float* __restrict__ x,
                 const float* __restrict__ y,
                 float* __restrict__ out)
{
    const int tx    = threadIdx.x;
    const int c0    = tx * 4;              // first output column of this thread
    const int plane = blockIdx.y;
    const int r0    = blockIdx.x * STRIP;  // first output row of this thread

    const size_t pbase = (size_t)plane * HH * WW;
    const float* xp = x + pbase;
    const float* yp = y + pbase;
    float* op       = out + pbase;

    // Column indices with reflect at the left/right image border.
    const int cm1 = (c0 == 0) ? 1 : c0 - 1;               // col c0-1
    const int cp4 = (c0 + 4 >= WW) ? (WW - 2) : (c0 + 4); // col c0+4

    // 3-row rotating register buffers: 6 columns (c0-1 .. c0+4), x and y.
    float xr[3][6], yr[3][6];

    // Preload rows r0-1 and r0 into slots 0 and 1.
    #pragma unroll
    for (int k = 0; k < 2; k++) {
        const int r = rrow(r0 - 1 + k);
        load_row6(xp + (size_t)r * WW, c0, cm1, cp4, xr[k]);
        load_row6(yp + (size_t)r * WW, c0, cm1, cp4, yr[k]);
    }

    const float inv9 = 1.0f / 9.0f;
    const float C1v  = 1.0e-4f;   // 0.01^2
    const float C2v  = 9.0e-4f;   // 0.03^2

    #pragma unroll
    for (int i = 0; i < STRIP; i++) {
        // Load input row (r0 + i + 1) into the rotating slot.
        {
            const int slot = (i + 2) % 3;
            const int r = rrow(r0 + i + 1);
            load_row6(xp + (size_t)r * WW, c0, cm1, cp4, xr[slot]);
            load_row6(yp + (size_t)r * WW, c0, cm1, cp4, yr[slot]);
        }

        const int s0 = i % 3, s1 = (i + 1) % 3, s2 = (i + 2) % 3;

        // Vertical (column) sums over the 3 rows for all 6 columns.
        float sx[6], sy[6], sxx[6], syy[6], sxy[6];
        #pragma unroll
        for (int j = 0; j < 6; j++) {
            const float a0 = xr[s0][j], a1 = xr[s1][j], a2 = xr[s2][j];
            const float b0 = yr[s0][j], b1 = yr[s1][j], b2 = yr[s2][j];
            sx[j]  = a0 + a1 + a2;
            sy[j]  = b0 + b1 + b2;
            sxx[j] = fmaf(a0, a0, fmaf(a1, a1, a2 * a2));
            syy[j] = fmaf(b0, b0, fmaf(b1, b1, b2 * b2));
            sxy[j] = fmaf(a0, b0, fmaf(a1, b1, a2 * b2));
        }

        // Horizontal sums + SSIM for 4 outputs.
        float resv[4];
        #pragma unroll
        for (int o = 0; o < 4; o++) {
            const float Sx  = sx[o]  + sx[o + 1]  + sx[o + 2];
            const float Sy  = sy[o]  + sy[o + 1]  + sy[o + 2];
            const float Sxx = sxx[o] + sxx[o + 1] + sxx[o + 2];
            const float Syy = syy[o] + syy[o + 1] + syy[o + 2];
            const float Sxy = sxy[o] + sxy[o + 1] + sxy[o + 2];

            const float mux = Sx * inv9;
            const float muy = Sy * inv9;
            const float mxx = mux * mux;
            const float myy = muy * muy;
            const float mxy = mux * muy;
            const float varx = fmaf(Sxx, inv9, -mxx);
            const float vary = fmaf(Syy, inv9, -myy);
            const float cov  = fmaf(Sxy, inv9, -mxy);

            const float num = fmaf(2.0f, mxy, C1v) * fmaf(2.0f, cov, C2v);
            const float den = (mxx + myy + C1v) * (varx + vary + C2v);
            float s = __fdividef(num, den);
            s = fminf(fmaxf(s, 0.0f), 1.0f);
            resv[o] = s;
        }

        float4 res = make_float4(resv[0], resv[1], resv[2], resv[3]);
        *(float4*)(op + (size_t)(r0 + i) * WW + c0) = res;
    }
}

extern "C" void kernel_launch(void* const* d_in, const int* in_sizes, int n_in,
                              void* d_out, int out_size) {
    const float* x = (const float*)d_in[0];
    const float* y = (const float*)d_in[1];
    float* out = (float*)d_out;

    const int planes = in_sizes[0] / (HH * WW);   // 32*3 = 96
    dim3 grid(HH / STRIP, planes);                // (48, 96)
    ssim_kernel<<<grid, TPB>>>(x, y, out);
}